// round 3
// baseline (speedup 1.0000x reference)
#include <cuda_runtime.h>
#include <cuda_fp16.h>
#include <cstdint>
#include <cstddef>

#define IN_DIM  4096
#define OUT_DIM 11008
#define B_DIM   8192

#define BM 128
#define BN 128
#define BK 32
#define STAGES 3
#define KT (IN_DIM / BK)   // 128 k-tiles

// Scratch: dequantized W in fp16, [OUT_DIM, IN_DIM] row-major (K contiguous),
// and x converted fp32 -> fp16.
static __device__ __half W_g[(size_t)OUT_DIM * (size_t)IN_DIM];
static __device__ __half X_g[(size_t)B_DIM   * (size_t)IN_DIM];

// ---------------------------------------------------------------------------
// Dequant: one thread handles 4 packed int32 values = 8 output elements
// (one 16B vectorized store). 8 consecutive elements always share the same
// primary (64) and secondary (256) quant block.
// ---------------------------------------------------------------------------
__global__ void __launch_bounds__(256) dequant_kernel(
    const int*   __restrict__ packed,
    const int*   __restrict__ absmax1,
    const float* __restrict__ code1,
    const float* __restrict__ offset1,
    const float* __restrict__ absmax2,
    const float* __restrict__ code2)
{
    int t = blockIdx.x * 256 + threadIdx.x;   // t in [0, P/4)
    int b1 = t >> 3;                          // primary block  (64 elems)
    int b2 = t >> 5;                          // secondary block (256 elems)
    float off = offset1[b1];
    float s = ((float)absmax1[b1] / code1[b1]) * (absmax2[b2] / code2[b2]);

    int4 p = reinterpret_cast<const int4*>(packed)[t];
    __half h[8];
    h[0] = __float2half_rn(((float)(p.x & 15) - off) * s);
    h[1] = __float2half_rn(((float)(p.x >> 4) - off) * s);
    h[2] = __float2half_rn(((float)(p.y & 15) - off) * s);
    h[3] = __float2half_rn(((float)(p.y >> 4) - off) * s);
    h[4] = __float2half_rn(((float)(p.z & 15) - off) * s);
    h[5] = __float2half_rn(((float)(p.z >> 4) - off) * s);
    h[6] = __float2half_rn(((float)(p.w & 15) - off) * s);
    h[7] = __float2half_rn(((float)(p.w >> 4) - off) * s);
    reinterpret_cast<float4*>(W_g)[t] = *reinterpret_cast<float4*>(h);
}

// ---------------------------------------------------------------------------
// Convert x: fp32 -> fp16. One thread = 8 elements (two float4 loads,
// one 16B store).
// ---------------------------------------------------------------------------
__global__ void __launch_bounds__(256) convert_x_kernel(
    const float* __restrict__ x)
{
    int t = blockIdx.x * 256 + threadIdx.x;   // t in [0, B*IN/8)
    float4 a = reinterpret_cast<const float4*>(x)[2 * t];
    float4 b = reinterpret_cast<const float4*>(x)[2 * t + 1];
    __half h[8];
    h[0] = __float2half_rn(a.x); h[1] = __float2half_rn(a.y);
    h[2] = __float2half_rn(a.z); h[3] = __float2half_rn(a.w);
    h[4] = __float2half_rn(b.x); h[5] = __float2half_rn(b.y);
    h[6] = __float2half_rn(b.z); h[7] = __float2half_rn(b.w);
    reinterpret_cast<float4*>(X_g)[t] = *reinterpret_cast<float4*>(h);
}

// ---------------------------------------------------------------------------
// GEMM: C[B_DIM, OUT_DIM] = X_g[B_DIM, IN_DIM] * W_g[OUT_DIM, IN_DIM]^T
// mma.sync m16n8k16, fp16 in / fp32 accum. 3-stage cp.async pipeline.
// Smem: XOR swizzle (chunk ^= (row>>1)&3) — conflict-free for both the
// 16B cp.async stores and the ldmatrix reads. 48 KB static total.
// Output written as fp32 (harness output dtype is float32).
// ---------------------------------------------------------------------------
__device__ __forceinline__ unsigned cvta_s(const void* p) {
    return (unsigned)__cvta_generic_to_shared(p);
}

__global__ void __launch_bounds__(256, 2) gemm_kernel(
    float* __restrict__ C)
{
    __shared__ __half sA[STAGES][BM * BK];
    __shared__ __half sB[STAGES][BN * BK];

    const int tid  = threadIdx.x;
    const int lane = tid & 31;
    const int warp = tid >> 5;
    const int wm   = warp >> 1;      // 0..3  (M direction)
    const int wn   = warp & 1;       // 0..1  (N direction)
    const int m0   = blockIdx.y * BM;
    const int n0   = blockIdx.x * BN;

    const __half* gA = X_g + (size_t)m0 * IN_DIM;
    const __half* gB = W_g + (size_t)n0 * IN_DIM;

    // Per-thread global->shared copy coords: 512 chunks of 16B per tile,
    // 256 threads -> 2 chunks each.
    const int r0c = tid >> 2;
    const int c0c = tid & 3;
    const int r1c = (tid + 256) >> 2;
    const int c1c = tid & 3;  // (tid+256)&3 == tid&3
    const unsigned soff0 = r0c * BK + ((c0c ^ ((r0c >> 1) & 3)) << 3);
    const unsigned soff1 = r1c * BK + ((c1c ^ ((r1c >> 1) & 3)) << 3);
    const size_t goff0 = (size_t)r0c * IN_DIM + (c0c << 3);
    const size_t goff1 = (size_t)r1c * IN_DIM + (c1c << 3);

    float acc[2][8][4];
    #pragma unroll
    for (int i = 0; i < 2; i++)
        #pragma unroll
        for (int n = 0; n < 8; n++)
            #pragma unroll
            for (int k = 0; k < 4; k++) acc[i][n][k] = 0.0f;

    auto issue_stage = [&](int s, int kb) {
        unsigned da0 = cvta_s(&sA[s][soff0]);
        unsigned da1 = cvta_s(&sA[s][soff1]);
        unsigned db0 = cvta_s(&sB[s][soff0]);
        unsigned db1 = cvta_s(&sB[s][soff1]);
        const __half* a0 = gA + kb + goff0;
        const __half* a1 = gA + kb + goff1;
        const __half* b0 = gB + kb + goff0;
        const __half* b1 = gB + kb + goff1;
        asm volatile("cp.async.cg.shared.global [%0], [%1], 16;" :: "r"(da0), "l"(a0));
        asm volatile("cp.async.cg.shared.global [%0], [%1], 16;" :: "r"(da1), "l"(a1));
        asm volatile("cp.async.cg.shared.global [%0], [%1], 16;" :: "r"(db0), "l"(b0));
        asm volatile("cp.async.cg.shared.global [%0], [%1], 16;" :: "r"(db1), "l"(b1));
    };

    // Prologue: stages 0..STAGES-2
    #pragma unroll
    for (int s = 0; s < STAGES - 1; s++) {
        issue_stage(s, s * BK);
        asm volatile("cp.async.commit_group;");
    }

    const int aRowB = wm * 32 + (lane & 15);
    const int aChB  = lane >> 4;
    const int bRowB = wn * 64 + ((lane >> 4) << 3) + (lane & 7);
    const int bChB  = (lane >> 3) & 1;

    for (int kt = 0; kt < KT; kt++) {
        const int nxt = kt + STAGES - 1;
        if (nxt < KT) issue_stage(nxt % STAGES, nxt * BK);
        asm volatile("cp.async.commit_group;");
        asm volatile("cp.async.wait_group %0;" :: "n"(STAGES - 2));
        __syncthreads();

        const __half* s_a = sA[kt % STAGES];
        const __half* s_b = sB[kt % STAGES];

        #pragma unroll
        for (int ks = 0; ks < BK / 16; ks++) {
            uint32_t a[2][4];
            #pragma unroll
            for (int i = 0; i < 2; i++) {
                const int r  = aRowB + i * 16;
                const int ch = (ks * 2 + aChB) ^ ((r >> 1) & 3);
                unsigned addr = cvta_s(s_a + r * BK + ch * 8);
                asm volatile(
                    "ldmatrix.sync.aligned.m8n8.x4.shared.b16 {%0,%1,%2,%3}, [%4];"
                    : "=r"(a[i][0]), "=r"(a[i][1]), "=r"(a[i][2]), "=r"(a[i][3])
                    : "r"(addr));
            }
            uint32_t b[4][4];
            #pragma unroll
            for (int j = 0; j < 4; j++) {
                const int r  = bRowB + j * 16;
                const int ch = (ks * 2 + bChB) ^ ((r >> 1) & 3);
                unsigned addr = cvta_s(s_b + r * BK + ch * 8);
                asm volatile(
                    "ldmatrix.sync.aligned.m8n8.x4.shared.b16 {%0,%1,%2,%3}, [%4];"
                    : "=r"(b[j][0]), "=r"(b[j][1]), "=r"(b[j][2]), "=r"(b[j][3])
                    : "r"(addr));
            }
            #pragma unroll
            for (int i = 0; i < 2; i++) {
                #pragma unroll
                for (int nt = 0; nt < 8; nt++) {
                    const int j  = nt >> 1;
                    const int hh = (nt & 1) << 1;
                    asm volatile(
                        "mma.sync.aligned.m16n8k16.row.col.f32.f16.f16.f32 "
                        "{%0,%1,%2,%3}, {%4,%5,%6,%7}, {%8,%9}, {%0,%1,%2,%3};"
                        : "+f"(acc[i][nt][0]), "+f"(acc[i][nt][1]),
                          "+f"(acc[i][nt][2]), "+f"(acc[i][nt][3])
                        : "r"(a[i][0]), "r"(a[i][1]), "r"(a[i][2]), "r"(a[i][3]),
                          "r"(b[j][hh]), "r"(b[j][hh + 1]));
                }
            }
        }
        __syncthreads();
    }

    // Epilogue: fp32 float2 stores straight to gmem.
    #pragma unroll
    for (int i = 0; i < 2; i++) {
        const int row = m0 + wm * 32 + i * 16 + (lane >> 2);
        #pragma unroll
        for (int nt = 0; nt < 8; nt++) {
            const int col = n0 + wn * 64 + nt * 8 + ((lane & 3) << 1);
            float2 v0 = make_float2(acc[i][nt][0], acc[i][nt][1]);
            float2 v1 = make_float2(acc[i][nt][2], acc[i][nt][3]);
            *reinterpret_cast<float2*>(C + (size_t)row * OUT_DIM + col) = v0;
            *reinterpret_cast<float2*>(C + (size_t)(row + 8) * OUT_DIM + col) = v1;
        }
    }
}

// ---------------------------------------------------------------------------
extern "C" void kernel_launch(void* const* d_in, const int* in_sizes, int n_in,
                              void* d_out, int out_size)
{
    const float*  x       = (const float*)d_in[0];
    const int*    packed  = (const int*)  d_in[1];
    const int*    absmax1 = (const int*)  d_in[2];
    const float*  code1   = (const float*)d_in[3];
    const float*  offset1 = (const float*)d_in[4];
    const float*  absmax2 = (const float*)d_in[5];
    const float*  code2   = (const float*)d_in[6];
    float* out = (float*)d_out;

    const int p4 = in_sizes[1] / 4;   // packed int32 count / 4, multiple of 256
    dequant_kernel<<<p4 / 256, 256>>>(packed, absmax1, code1, offset1,
                                      absmax2, code2);

    const int xv = in_sizes[0] / 8;   // 4,194,304 threads, multiple of 256
    convert_x_kernel<<<xv / 256, 256>>>(x);

    dim3 grid(OUT_DIM / BN, B_DIM / BM);   // (86, 64)
    gemm_kernel<<<grid, 256>>>(out);
}

// round 8
// speedup vs baseline: 1.0050x; 1.0050x over previous
#include <cuda_runtime.h>
#include <cuda_fp16.h>
#include <cstdint>
#include <cstddef>

#define IN_DIM  4096
#define OUT_DIM 11008
#define B_DIM   8192

#define BM 128
#define BN 256
#define BK 64
#define STAGES 3
#define KT (IN_DIM / BK)            // 64 k-tiles

// smem stage sizes: rows are 64 halfs = 128 bytes (SW128-style swizzle domain)
#define A_STAGE_BYTES (BM * BK * 2)   // 16384
#define B_STAGE_BYTES (BN * BK * 2)   // 32768
#define DSMEM_BYTES (STAGES * (A_STAGE_BYTES + B_STAGE_BYTES))   // 147456

// Scratch: dequantized W fp16 [OUT, IN] K-contiguous; x converted fp32->fp16.
static __device__ __half W_g[(size_t)OUT_DIM * (size_t)IN_DIM];
static __device__ __half X_g[(size_t)B_DIM   * (size_t)IN_DIM];

// ---------------------------------------------------------------------------
__global__ void __launch_bounds__(256) dequant_kernel(
    const int*   __restrict__ packed,
    const int*   __restrict__ absmax1,
    const float* __restrict__ code1,
    const float* __restrict__ offset1,
    const float* __restrict__ absmax2,
    const float* __restrict__ code2)
{
    int t = blockIdx.x * 256 + threadIdx.x;
    int b1 = t >> 3;
    int b2 = t >> 5;
    float off = offset1[b1];
    float s = ((float)absmax1[b1] / code1[b1]) * (absmax2[b2] / code2[b2]);

    int4 p = reinterpret_cast<const int4*>(packed)[t];
    __half h[8];
    h[0] = __float2half_rn(((float)(p.x & 15) - off) * s);
    h[1] = __float2half_rn(((float)(p.x >> 4) - off) * s);
    h[2] = __float2half_rn(((float)(p.y & 15) - off) * s);
    h[3] = __float2half_rn(((float)(p.y >> 4) - off) * s);
    h[4] = __float2half_rn(((float)(p.z & 15) - off) * s);
    h[5] = __float2half_rn(((float)(p.z >> 4) - off) * s);
    h[6] = __float2half_rn(((float)(p.w & 15) - off) * s);
    h[7] = __float2half_rn(((float)(p.w >> 4) - off) * s);
    reinterpret_cast<float4*>(W_g)[t] = *reinterpret_cast<float4*>(h);
}

__global__ void __launch_bounds__(256) convert_x_kernel(const float* __restrict__ x)
{
    int t = blockIdx.x * 256 + threadIdx.x;
    float4 a = reinterpret_cast<const float4*>(x)[2 * t];
    float4 b = reinterpret_cast<const float4*>(x)[2 * t + 1];
    __half h[8];
    h[0] = __float2half_rn(a.x); h[1] = __float2half_rn(a.y);
    h[2] = __float2half_rn(a.z); h[3] = __float2half_rn(a.w);
    h[4] = __float2half_rn(b.x); h[5] = __float2half_rn(b.y);
    h[6] = __float2half_rn(b.z); h[7] = __float2half_rn(b.w);
    reinterpret_cast<float4*>(X_g)[t] = *reinterpret_cast<float4*>(h);
}

// ---------------------------------------------------------------------------
__device__ __forceinline__ unsigned cvta_s(const void* p) {
    return (unsigned)__cvta_generic_to_shared(p);
}

// ---------------------------------------------------------------------------
// GEMM: C[B_DIM, OUT_DIM] = X_g * W_g^T.  CTA tile 128x256, BK=64, 3 stages.
// mma.sync m16n8k16 fp16->fp32. 8 warps in 4(M) x 2(N); warp tile 32x128.
// Swizzle: byte offset within a 128B row XORed by ((off>>3)&0x70) — identical
// function for cp.async stores and ldmatrix reads; conflict-free both ways.
// CTA raster: 8-m-tile supertiles for L2 reuse of W.
// ---------------------------------------------------------------------------
__global__ void __launch_bounds__(256, 1) gemm_kernel(float* __restrict__ C)
{
    extern __shared__ __align__(16) char dyn_smem[];
    __half* sA = reinterpret_cast<__half*>(dyn_smem);
    __half* sB = reinterpret_cast<__half*>(dyn_smem + STAGES * A_STAGE_BYTES);

    const int tid  = threadIdx.x;
    const int lane = tid & 31;
    const int warp = tid >> 5;
    const int wm   = warp >> 1;      // 0..3
    const int wn   = warp & 1;       // 0..1

    // Supertile raster: 8 m-tiles tall, all 43 n-tiles wide.
    const int id    = blockIdx.x;           // 0..2751
    const int group = id / (43 * 8);        // 0..7
    const int rem   = id % (43 * 8);
    const int n0    = (rem / 8) * BN;
    const int m0    = (group * 8 + (rem & 7)) * BM;

    const __half* gA = X_g + (size_t)m0 * IN_DIM;
    const __half* gB = W_g + (size_t)n0 * IN_DIM;

    float acc[2][16][4];
    #pragma unroll
    for (int i = 0; i < 2; i++)
        #pragma unroll
        for (int n = 0; n < 16; n++)
            #pragma unroll
            for (int k = 0; k < 4; k++) acc[i][n][k] = 0.0f;

    // Stage copy: A = 1024 16B chunks, B = 2048 chunks; 256 threads.
    // chunk c -> row = c>>3, colchunk = c&7 (8 x 16B = 128B per row).
    auto issue_stage = [&](int st, int kb) {
        char* aBase = dyn_smem + st * A_STAGE_BYTES;
        char* bBase = dyn_smem + STAGES * A_STAGE_BYTES + st * B_STAGE_BYTES;
        #pragma unroll
        for (int i = 0; i < 4; i++) {
            int c = tid + i * 256;
            int row = c >> 3, col = c & 7;
            uint32_t off = (row << 7) + (col << 4);
            uint32_t sw  = off ^ ((off >> 3) & 0x70);
            const __half* src = gA + (size_t)row * IN_DIM + kb + col * 8;
            asm volatile("cp.async.cg.shared.global [%0], [%1], 16;"
                         :: "r"(cvta_s(aBase + sw)), "l"(src));
        }
        #pragma unroll
        for (int i = 0; i < 8; i++) {
            int c = tid + i * 256;
            int row = c >> 3, col = c & 7;
            uint32_t off = (row << 7) + (col << 4);
            uint32_t sw  = off ^ ((off >> 3) & 0x70);
            const __half* src = gB + (size_t)row * IN_DIM + kb + col * 8;
            asm volatile("cp.async.cg.shared.global [%0], [%1], 16;"
                         :: "r"(cvta_s(bBase + sw)), "l"(src));
        }
    };

    #pragma unroll
    for (int s = 0; s < STAGES - 1; s++) {
        issue_stage(s, s * BK);
        asm volatile("cp.async.commit_group;");
    }

    // Fragment lane addressing (validated in the R3-passing kernel):
    // A: lanes 0-15 -> rows m..m+15 chunk ks*2 (k0-7); lanes 16-31 -> chunk ks*2+1.
    // B: lanes {0-7,8-15,16-23,24-31} -> rows {n0-7,n0-7,n8-15,n8-15} with
    //    chunk parity (lane>>3)&1.
    const int aRowB = wm * 32 + (lane & 15);
    const int aChB  = lane >> 4;
    const int bRowB = wn * 128 + ((lane >> 4) << 3) + (lane & 7);
    const int bChB  = (lane >> 3) & 1;

    for (int kt = 0; kt < KT; kt++) {
        const int nxt = kt + STAGES - 1;
        if (nxt < KT) issue_stage(nxt % STAGES, nxt * BK);
        asm volatile("cp.async.commit_group;");
        asm volatile("cp.async.wait_group %0;" :: "n"(STAGES - 2));
        __syncthreads();

        const char* s_a = dyn_smem + (kt % STAGES) * A_STAGE_BYTES;
        const char* s_b = dyn_smem + STAGES * A_STAGE_BYTES
                                   + (kt % STAGES) * B_STAGE_BYTES;

        #pragma unroll
        for (int ks = 0; ks < BK / 16; ks++) {
            uint32_t a[2][4];
            #pragma unroll
            for (int i = 0; i < 2; i++) {
                const int r = aRowB + i * 16;
                uint32_t off = (r << 7) + ((ks * 2 + aChB) << 4);
                uint32_t sw  = off ^ ((off >> 3) & 0x70);
                asm volatile(
                    "ldmatrix.sync.aligned.m8n8.x4.shared.b16 {%0,%1,%2,%3}, [%4];"
                    : "=r"(a[i][0]), "=r"(a[i][1]), "=r"(a[i][2]), "=r"(a[i][3])
                    : "r"(cvta_s(s_a + sw)));
            }
            uint32_t b[8][4];
            #pragma unroll
            for (int j = 0; j < 8; j++) {
                const int r = bRowB + j * 16;
                uint32_t off = (r << 7) + ((ks * 2 + bChB) << 4);
                uint32_t sw  = off ^ ((off >> 3) & 0x70);
                asm volatile(
                    "ldmatrix.sync.aligned.m8n8.x4.shared.b16 {%0,%1,%2,%3}, [%4];"
                    : "=r"(b[j][0]), "=r"(b[j][1]), "=r"(b[j][2]), "=r"(b[j][3])
                    : "r"(cvta_s(s_b + sw)));
            }
            #pragma unroll
            for (int i = 0; i < 2; i++) {
                #pragma unroll
                for (int nt = 0; nt < 16; nt++) {
                    const int j  = nt >> 1;
                    const int hh = (nt & 1) << 1;
                    asm volatile(
                        "mma.sync.aligned.m16n8k16.row.col.f32.f16.f16.f32 "
                        "{%0,%1,%2,%3}, {%4,%5,%6,%7}, {%8,%9}, {%0,%1,%2,%3};"
                        : "+f"(acc[i][nt][0]), "+f"(acc[i][nt][1]),
                          "+f"(acc[i][nt][2]), "+f"(acc[i][nt][3])
                        : "r"(a[i][0]), "r"(a[i][1]), "r"(a[i][2]), "r"(a[i][3]),
                          "r"(b[j][hh]), "r"(b[j][hh + 1]));
                }
            }
        }
        __syncthreads();
    }

    // Epilogue: fp32 float2 stores.
    #pragma unroll
    for (int i = 0; i < 2; i++) {
        const int row = m0 + wm * 32 + i * 16 + (lane >> 2);
        #pragma unroll
        for (int nt = 0; nt < 16; nt++) {
            const int col = n0 + wn * 128 + nt * 8 + ((lane & 3) << 1);
            *reinterpret_cast<float2*>(C + (size_t)row * OUT_DIM + col) =
                make_float2(acc[i][nt][0], acc[i][nt][1]);
            *reinterpret_cast<float2*>(C + (size_t)(row + 8) * OUT_DIM + col) =
                make_float2(acc[i][nt][2], acc[i][nt][3]);
        }
    }
}

// ---------------------------------------------------------------------------
extern "C" void kernel_launch(void* const* d_in, const int* in_sizes, int n_in,
                              void* d_out, int out_size)
{
    const float*  x       = (const float*)d_in[0];
    const int*    packed  = (const int*)  d_in[1];
    const int*    absmax1 = (const int*)  d_in[2];
    const float*  code1   = (const float*)d_in[3];
    const float*  offset1 = (const float*)d_in[4];
    const float*  absmax2 = (const float*)d_in[5];
    const float*  code2   = (const float*)d_in[6];
    float* out = (float*)d_out;

    const int p4 = in_sizes[1] / 4;
    dequant_kernel<<<p4 / 256, 256>>>(packed, absmax1, code1, offset1,
                                      absmax2, code2);

    const int xv = in_sizes[0] / 8;
    convert_x_kernel<<<xv / 256, 256>>>(x);

    static int smem_set = 0;
    if (!smem_set) {
        cudaFuncSetAttribute(gemm_kernel,
                             cudaFuncAttributeMaxDynamicSharedMemorySize,
                             DSMEM_BYTES);
        smem_set = 1;
    }
    const int nblocks = (OUT_DIM / BN) * (B_DIM / BM);   // 43 * 64 = 2752
    gemm_kernel<<<nblocks, 256, DSMEM_BYTES>>>(out);
}

// round 14
// speedup vs baseline: 1.0448x; 1.0396x over previous
#include <cuda_runtime.h>
#include <cuda_fp16.h>
#include <cstdint>
#include <cstddef>

#define IN_DIM  4096
#define OUT_DIM 11008
#define B_DIM   8192

#define BM 128
#define BN 256
#define BK 64
#define STAGES 4
#define KT (IN_DIM / BK)            // 64 k-tiles

#define A_STAGE_BYTES (BM * BK * 2)   // 16384
#define B_STAGE_BYTES (BN * BK * 2)   // 32768
#define DSMEM_BYTES (STAGES * (A_STAGE_BYTES + B_STAGE_BYTES))   // 196608

// Scratch: dequantized W fp16 [OUT, IN] K-contiguous; x converted fp32->fp16.
static __device__ __half W_g[(size_t)OUT_DIM * (size_t)IN_DIM];
static __device__ __half X_g[(size_t)B_DIM   * (size_t)IN_DIM];

#define DQ_BLOCKS 22016   // (P/4)/256
#define CV_BLOCKS 16384   // (B*IN/8)/256

// ---------------------------------------------------------------------------
// Merged prep: blocks [0, DQ_BLOCKS) dequantize W; rest convert x fp32->fp16.
// ---------------------------------------------------------------------------
__global__ void __launch_bounds__(256) prep_kernel(
    const float* __restrict__ x,
    const int*   __restrict__ packed,
    const int*   __restrict__ absmax1,
    const float* __restrict__ code1,
    const float* __restrict__ offset1,
    const float* __restrict__ absmax2,
    const float* __restrict__ code2)
{
    if (blockIdx.x < DQ_BLOCKS) {
        int t = blockIdx.x * 256 + threadIdx.x;
        int b1 = t >> 3;
        int b2 = t >> 5;
        float off = offset1[b1];
        float s = ((float)absmax1[b1] / code1[b1]) * (absmax2[b2] / code2[b2]);

        int4 p = reinterpret_cast<const int4*>(packed)[t];
        __half h[8];
        h[0] = __float2half_rn(((float)(p.x & 15) - off) * s);
        h[1] = __float2half_rn(((float)(p.x >> 4) - off) * s);
        h[2] = __float2half_rn(((float)(p.y & 15) - off) * s);
        h[3] = __float2half_rn(((float)(p.y >> 4) - off) * s);
        h[4] = __float2half_rn(((float)(p.z & 15) - off) * s);
        h[5] = __float2half_rn(((float)(p.z >> 4) - off) * s);
        h[6] = __float2half_rn(((float)(p.w & 15) - off) * s);
        h[7] = __float2half_rn(((float)(p.w >> 4) - off) * s);
        reinterpret_cast<float4*>(W_g)[t] = *reinterpret_cast<float4*>(h);
    } else {
        int t = (blockIdx.x - DQ_BLOCKS) * 256 + threadIdx.x;
        float4 a = reinterpret_cast<const float4*>(x)[2 * t];
        float4 b = reinterpret_cast<const float4*>(x)[2 * t + 1];
        __half h[8];
        h[0] = __float2half_rn(a.x); h[1] = __float2half_rn(a.y);
        h[2] = __float2half_rn(a.z); h[3] = __float2half_rn(a.w);
        h[4] = __float2half_rn(b.x); h[5] = __float2half_rn(b.y);
        h[6] = __float2half_rn(b.z); h[7] = __float2half_rn(b.w);
        reinterpret_cast<float4*>(X_g)[t] = *reinterpret_cast<float4*>(h);
    }
}

// ---------------------------------------------------------------------------
__device__ __forceinline__ unsigned cvta_s(const void* p) {
    return (unsigned)__cvta_generic_to_shared(p);
}

// ---------------------------------------------------------------------------
// GEMM: C = X_g * W_g^T. CTA tile 128x256, BK=64, 4 stages, ONE sync/iter.
// mma.sync m16n8k16 fp16->fp32, 8 warps 4(M)x2(N), warp tile 32x128.
// Swizzle identical to verified R8 kernel.
// ---------------------------------------------------------------------------
__global__ void __launch_bounds__(256, 1) gemm_kernel(float* __restrict__ C)
{
    extern __shared__ __align__(16) char dyn_smem[];

    const int tid  = threadIdx.x;
    const int lane = tid & 31;
    const int warp = tid >> 5;
    const int wm   = warp >> 1;      // 0..3
    const int wn   = warp & 1;       // 0..1

    // Supertile raster: 8 m-tiles tall, all 43 n-tiles wide.
    const int id    = blockIdx.x;
    const int group = id / (43 * 8);
    const int rem   = id % (43 * 8);
    const int n0    = (rem / 8) * BN;
    const int m0    = (group * 8 + (rem & 7)) * BM;

    const __half* gA = X_g + (size_t)m0 * IN_DIM;
    const __half* gB = W_g + (size_t)n0 * IN_DIM;

    float acc[2][16][4];
    #pragma unroll
    for (int i = 0; i < 2; i++)
        #pragma unroll
        for (int n = 0; n < 16; n++)
            #pragma unroll
            for (int k = 0; k < 4; k++) acc[i][n][k] = 0.0f;

    auto issue_stage = [&](int st, int kb) {
        char* aBase = dyn_smem + st * A_STAGE_BYTES;
        char* bBase = dyn_smem + STAGES * A_STAGE_BYTES + st * B_STAGE_BYTES;
        #pragma unroll
        for (int i = 0; i < 4; i++) {
            int c = tid + i * 256;
            int row = c >> 3, col = c & 7;
            uint32_t off = (row << 7) + (col << 4);
            uint32_t sw  = off ^ ((off >> 3) & 0x70);
            const __half* src = gA + (size_t)row * IN_DIM + kb + col * 8;
            asm volatile("cp.async.cg.shared.global [%0], [%1], 16;"
                         :: "r"(cvta_s(aBase + sw)), "l"(src));
        }
        #pragma unroll
        for (int i = 0; i < 8; i++) {
            int c = tid + i * 256;
            int row = c >> 3, col = c & 7;
            uint32_t off = (row << 7) + (col << 4);
            uint32_t sw  = off ^ ((off >> 3) & 0x70);
            const __half* src = gB + (size_t)row * IN_DIM + kb + col * 8;
            asm volatile("cp.async.cg.shared.global [%0], [%1], 16;"
                         :: "r"(cvta_s(bBase + sw)), "l"(src));
        }
    };

    // Prologue: stages 0..STAGES-2 (3 groups in flight)
    #pragma unroll
    for (int s = 0; s < STAGES - 1; s++) {
        issue_stage(s, s * BK);
        asm volatile("cp.async.commit_group;");
    }

    const int aRowB = wm * 32 + (lane & 15);
    const int aChB  = lane >> 4;
    const int bRowB = wn * 128 + ((lane >> 4) << 3) + (lane & 7);
    const int bChB  = (lane >> 3) & 1;

    for (int kt = 0; kt < KT; kt++) {
        // Stage kt ready when <= STAGES-2 groups outstanding.
        asm volatile("cp.async.wait_group %0;" :: "n"(STAGES - 2));
        __syncthreads();
        // All warps finished reading stage kt-1 (program order) -> safe to
        // overwrite it with stage kt+STAGES-1.
        const int nxt = kt + STAGES - 1;
        if (nxt < KT) {
            issue_stage(nxt % STAGES, nxt * BK);
            asm volatile("cp.async.commit_group;");
        } else {
            asm volatile("cp.async.commit_group;");  // empty group keeps counts aligned
        }

        const char* s_a = dyn_smem + (kt % STAGES) * A_STAGE_BYTES;
        const char* s_b = dyn_smem + STAGES * A_STAGE_BYTES
                                   + (kt % STAGES) * B_STAGE_BYTES;

        #pragma unroll
        for (int ks = 0; ks < BK / 16; ks++) {
            uint32_t a[2][4];
            #pragma unroll
            for (int i = 0; i < 2; i++) {
                const int r = aRowB + i * 16;
                uint32_t off = (r << 7) + ((ks * 2 + aChB) << 4);
                uint32_t sw  = off ^ ((off >> 3) & 0x70);
                asm volatile(
                    "ldmatrix.sync.aligned.m8n8.x4.shared.b16 {%0,%1,%2,%3}, [%4];"
                    : "=r"(a[i][0]), "=r"(a[i][1]), "=r"(a[i][2]), "=r"(a[i][3])
                    : "r"(cvta_s(s_a + sw)));
            }
            uint32_t b[8][4];
            #pragma unroll
            for (int j = 0; j < 8; j++) {
                const int r = bRowB + j * 16;
                uint32_t off = (r << 7) + ((ks * 2 + bChB) << 4);
                uint32_t sw  = off ^ ((off >> 3) & 0x70);
                asm volatile(
                    "ldmatrix.sync.aligned.m8n8.x4.shared.b16 {%0,%1,%2,%3}, [%4];"
                    : "=r"(b[j][0]), "=r"(b[j][1]), "=r"(b[j][2]), "=r"(b[j][3])
                    : "r"(cvta_s(s_b + sw)));
            }
            #pragma unroll
            for (int i = 0; i < 2; i++) {
                #pragma unroll
                for (int nt = 0; nt < 16; nt++) {
                    const int j  = nt >> 1;
                    const int hh = (nt & 1) << 1;
                    asm volatile(
                        "mma.sync.aligned.m16n8k16.row.col.f32.f16.f16.f32 "
                        "{%0,%1,%2,%3}, {%4,%5,%6,%7}, {%8,%9}, {%0,%1,%2,%3};"
                        : "+f"(acc[i][nt][0]), "+f"(acc[i][nt][1]),
                          "+f"(acc[i][nt][2]), "+f"(acc[i][nt][3])
                        : "r"(a[i][0]), "r"(a[i][1]), "r"(a[i][2]), "r"(a[i][3]),
                          "r"(b[j][hh]), "r"(b[j][hh + 1]));
                }
            }
        }
    }

    // Epilogue: fp32 float2 stores.
    #pragma unroll
    for (int i = 0; i < 2; i++) {
        const int row = m0 + wm * 32 + i * 16 + (lane >> 2);
        #pragma unroll
        for (int nt = 0; nt < 16; nt++) {
            const int col = n0 + wn * 128 + nt * 8 + ((lane & 3) << 1);
            *reinterpret_cast<float2*>(C + (size_t)row * OUT_DIM + col) =
                make_float2(acc[i][nt][0], acc[i][nt][1]);
            *reinterpret_cast<float2*>(C + (size_t)(row + 8) * OUT_DIM + col) =
                make_float2(acc[i][nt][2], acc[i][nt][3]);
        }
    }
}

// ---------------------------------------------------------------------------
extern "C" void kernel_launch(void* const* d_in, const int* in_sizes, int n_in,
                              void* d_out, int out_size)
{
    const float*  x       = (const float*)d_in[0];
    const int*    packed  = (const int*)  d_in[1];
    const int*    absmax1 = (const int*)  d_in[2];
    const float*  code1   = (const float*)d_in[3];
    const float*  offset1 = (const float*)d_in[4];
    const float*  absmax2 = (const float*)d_in[5];
    const float*  code2   = (const float*)d_in[6];
    float* out = (float*)d_out;

    prep_kernel<<<DQ_BLOCKS + CV_BLOCKS, 256>>>(x, packed, absmax1, code1,
                                                offset1, absmax2, code2);

    static int smem_set = 0;
    if (!smem_set) {
        cudaFuncSetAttribute(gemm_kernel,
                             cudaFuncAttributeMaxDynamicSharedMemorySize,
                             DSMEM_BYTES);
        smem_set = 1;
    }
    const int nblocks = (OUT_DIM / BN) * (B_DIM / BM);   // 2752
    gemm_kernel<<<nblocks, 256, DSMEM_BYTES>>>(out);
}